// round 6
// baseline (speedup 1.0000x reference)
#include <cuda_runtime.h>
#include <cuda_bf16.h>
#include <math.h>
#include <stdint.h>

// Problem constants
#define BZ       16
#define SEG_LEN  16
#define NUM_SEGS 256
#define HH       512
#define NHH      8
#define HD       64
#define SS       4097                 // NUM_SEGS*SEG_LEN + 1
#define NSEG     (BZ * NUM_SEGS)     // 4096
#define LL       18                  // SEG_LEN + 2
#define TOK      (NSEG * LL)         // 73728
#define FTOK     (BZ * SS)           // 65552 (FFN tokens)
#define LN_EPS   1e-5f

// ---------------- scratch (__device__ globals; zero-init bss) ----------------
__device__ float g_segs[(size_t)TOK * HH];
__device__ float g_q   [(size_t)TOK * HH];
__device__ float g_k   [(size_t)TOK * HH];
__device__ float g_v   [(size_t)TOK * HH];
__device__ float g_att [(size_t)TOK * HH];
__device__ float g_o   [(size_t)TOK * HH];
__device__ float g_proc[(size_t)FTOK * HH];
__device__ float g_act [(size_t)FTOK * 2 * HH];

// ---------------- build segs: [N_seg, 18, H] with start/end markers ----------
__global__ void build_segs_kernel(const float* __restrict__ hid,
                                  const float* __restrict__ st,
                                  const float* __restrict__ en) {
    size_t i4 = (size_t)blockIdx.x * blockDim.x + threadIdx.x;
    int row = (int)(i4 / (HH / 4));
    int c4  = (int)(i4 % (HH / 4));
    int n = row / LL, l = row % LL;
    const float4* src;
    if (l == 0)            src = (const float4*)st;
    else if (l == LL - 1)  src = (const float4*)en;
    else {
        int b = n / NUM_SEGS, seg = n % NUM_SEGS;
        src = (const float4*)(hid + ((size_t)b * SS + (size_t)seg * SEG_LEN + (l - 1)) * HH);
    }
    ((float4*)g_segs)[i4] = src[c4];
}

// ---------------- TF32 tensor-core GEMM (5-stage cp.async, 128x256 block) ----
// C[M,N] = A[M,K] @ W[K,N] + bias (+epilogue); up to 3 fused output matrices.
// EPI: 0 = +bias ; 1 = gelu(x+bias) ; 2 = x+bias+res[row,col]
struct GemmMats {
    const float* W[3];
    const float* bias[3];
    float* C[3];
};

__device__ __forceinline__ float gelu_exact(float x) {
    return 0.5f * x * (1.0f + erff(x * 0.70710678118654752f));
}

__device__ __forceinline__ void cpa16(float* smem_dst, const float* gsrc) {
    uint32_t s = (uint32_t)__cvta_generic_to_shared(smem_dst);
    asm volatile("cp.async.cg.shared.global [%0], [%1], 16;\n" :: "r"(s), "l"(gsrc));
}

#define ASTR   20                    // As row stride (floats), conflict-free
#define BSTR   264                   // Bs row stride (floats), conflict-free
#define A_STG  (128 * ASTR)          // floats per A stage
#define B_STG  (16 * BSTR)           // floats per B stage
#define NSTAGE 5
#define GEMM_SMEM ((NSTAGE * (A_STG + B_STG)) * 4)   // 135,680 bytes

template <int EPI>
__global__ __launch_bounds__(256, 1)
void tgemm_kernel(const float* __restrict__ A, GemmMats mats, int nblk,
                  const float* __restrict__ res, int M, int N, int K) {
    extern __shared__ float sm[];
    float* As = sm;                       // [NSTAGE][128][ASTR]
    float* Bs = sm + NSTAGE * A_STG;      // [NSTAGE][16][BSTR]

    const int tid  = threadIdx.x;
    const int warp = tid >> 5;
    const int lane = tid & 31;
    const int g    = lane >> 2;   // 0..7
    const int tig  = lane & 3;    // 0..3

    const int wsel = blockIdx.x / nblk;
    const int n0   = (blockIdx.x % nblk) * 256;
    const float* W    = mats.W[wsel];
    const float* bias = mats.bias[wsel];
    float*       C    = mats.C[wsel];

    const int m0 = blockIdx.y * 128;
    const int warp_m = (warp & 1) * 64;    // 2 warps in M
    const int warp_n = (warp >> 1) * 64;   // 4 warps in N

    // A loader: row = tid>>1, 8 floats (2 x cpa16) along k
    int arow = m0 + (tid >> 1); if (arow > M - 1) arow = M - 1;
    const float* Ag = A + (size_t)arow * K + (tid & 1) * 8;
    float* Asd = As + (tid >> 1) * ASTR + (tid & 1) * 8;
    // B loader: krow = tid>>4 (0..15), 16 floats (4 x cpa16) along n
    const int bkrow = tid >> 4;
    const int bc    = (tid & 15) * 16;
    const float* Bg = W + (size_t)bkrow * N + n0 + bc;
    float* Bsd = Bs + bkrow * BSTR + bc;

    const int nk = K >> 4;

    auto issue_body = [&](int kt) {
        int buf = kt % NSTAGE;
        const float* ag = Ag + kt * 16;
        float* ad = Asd + buf * A_STG;
        cpa16(ad, ag); cpa16(ad + 4, ag + 4);
        const float* bg = Bg + (size_t)kt * 16 * N;
        float* bd = Bsd + buf * B_STG;
#pragma unroll
        for (int j = 0; j < 4; j++) cpa16(bd + j * 4, bg + j * 4);
    };

    float acc[4][8][4];
#pragma unroll
    for (int i = 0; i < 4; i++)
#pragma unroll
        for (int j = 0; j < 8; j++)
#pragma unroll
            for (int c = 0; c < 4; c++) acc[i][j][c] = 0.f;

    uint32_t af[2][4][4], bf[2][8][2];

    auto ldfrag = [&](int ph, int ks, const uint32_t* as, const uint32_t* bs) {
#pragma unroll
        for (int mt = 0; mt < 4; mt++) {
            int r = warp_m + mt * 16 + g;
            af[ph][mt][0] = as[(r    ) * ASTR + ks + tig];
            af[ph][mt][1] = as[(r + 8) * ASTR + ks + tig];
            af[ph][mt][2] = as[(r    ) * ASTR + ks + tig + 4];
            af[ph][mt][3] = as[(r + 8) * ASTR + ks + tig + 4];
        }
#pragma unroll
        for (int nt = 0; nt < 8; nt++) {
            int cc = warp_n + nt * 8 + g;
            bf[ph][nt][0] = bs[(ks + tig    ) * BSTR + cc];
            bf[ph][nt][1] = bs[(ks + tig + 4) * BSTR + cc];
        }
    };
    auto domma = [&](int ph) {
#pragma unroll
        for (int mt = 0; mt < 4; mt++)
#pragma unroll
            for (int nt = 0; nt < 8; nt++) {
                asm volatile(
                    "mma.sync.aligned.m16n8k8.row.col.f32.tf32.tf32.f32 "
                    "{%0,%1,%2,%3}, {%4,%5,%6,%7}, {%8,%9}, {%0,%1,%2,%3};\n"
                    : "+f"(acc[mt][nt][0]), "+f"(acc[mt][nt][1]),
                      "+f"(acc[mt][nt][2]), "+f"(acc[mt][nt][3])
                    : "r"(af[ph][mt][0]), "r"(af[ph][mt][1]),
                      "r"(af[ph][mt][2]), "r"(af[ph][mt][3]),
                      "r"(bf[ph][nt][0]), "r"(bf[ph][nt][1]));
            }
    };

    // prologue: 4 stages in flight
#pragma unroll
    for (int p = 0; p < 4; p++) {
        if (p < nk) issue_body(p);
        asm volatile("cp.async.commit_group;\n");
    }

    for (int kt = 0; kt < nk; kt++) {
        asm volatile("cp.async.wait_group 3;\n");
        __syncthreads();
        const uint32_t* as = (const uint32_t*)(As + (kt % NSTAGE) * A_STG);
        const uint32_t* bs = (const uint32_t*)(Bs + (kt % NSTAGE) * B_STG);
        ldfrag(0, 0, as, bs);   // frags for ks=0
        ldfrag(1, 8, as, bs);   // frags for ks=8 (overlaps with mma of phase 0)
        domma(0);
        domma(1);
        if (kt + 4 < nk) issue_body(kt + 4);
        asm volatile("cp.async.commit_group;\n");   // may be empty (tail)
    }

    // epilogue
#pragma unroll
    for (int nt = 0; nt < 8; nt++) {
        int col = n0 + warp_n + nt * 8 + 2 * tig;
        float bx = bias[col], by = bias[col + 1];
#pragma unroll
        for (int mt = 0; mt < 4; mt++) {
            int r0 = m0 + warp_m + mt * 16 + g;
            int r1 = r0 + 8;
            float v0 = acc[mt][nt][0] + bx, v1 = acc[mt][nt][1] + by;
            float v2 = acc[mt][nt][2] + bx, v3 = acc[mt][nt][3] + by;
            if (EPI == 1) {
                v0 = gelu_exact(v0); v1 = gelu_exact(v1);
                v2 = gelu_exact(v2); v3 = gelu_exact(v3);
            }
            if (r0 < M) {
                if (EPI == 2) {
                    const float2 rr = *(const float2*)(res + (size_t)r0 * N + col);
                    v0 += rr.x; v1 += rr.y;
                }
                *(float2*)(C + (size_t)r0 * N + col) = make_float2(v0, v1);
            }
            if (r1 < M) {
                if (EPI == 2) {
                    const float2 rr = *(const float2*)(res + (size_t)r1 * N + col);
                    v2 += rr.x; v3 += rr.y;
                }
                *(float2*)(C + (size_t)r1 * N + col) = make_float2(v2, v3);
            }
        }
    }
}

// ---------------- attention per (segment, head) ------------------------------
__global__ __launch_bounds__(128)
void attn_kernel(const float* __restrict__ q, const float* __restrict__ k,
                 const float* __restrict__ v, float* __restrict__ out) {
    const int n = blockIdx.x >> 3;
    const int h = blockIdx.x & 7;
    __shared__ float qs[LL * HD], ks[LL * HD], vs[LL * HD];
    __shared__ float sc[LL][LL];

    const size_t base = (size_t)n * LL * HH + (size_t)h * HD;
    for (int i = threadIdx.x; i < LL * HD; i += 128) {
        int r = i >> 6, c = i & 63;
        size_t idx = base + (size_t)r * HH + c;
        qs[i] = q[idx];
        ks[i] = k[idx];
        vs[i] = v[idx];
    }
    __syncthreads();

    for (int s = threadIdx.x; s < LL * LL; s += 128) {
        int qi = s / LL, kj = s % LL;
        float d = 0.f;
#pragma unroll
        for (int c = 0; c < HD; c++) d = fmaf(qs[qi * HD + c], ks[kj * HD + c], d);
        sc[qi][kj] = d * 0.125f;  // 1/sqrt(64)
    }
    __syncthreads();

    if (threadIdx.x < LL) {
        int r = threadIdx.x;
        float m = -1e30f;
#pragma unroll
        for (int j = 0; j < LL; j++) m = fmaxf(m, sc[r][j]);
        float sum = 0.f;
#pragma unroll
        for (int j = 0; j < LL; j++) { float e = __expf(sc[r][j] - m); sc[r][j] = e; sum += e; }
        float inv = 1.f / sum;
#pragma unroll
        for (int j = 0; j < LL; j++) sc[r][j] *= inv;
    }
    __syncthreads();

    for (int s = threadIdx.x; s < LL * HD; s += 128) {
        int qi = s >> 6, d = s & 63;
        float a = 0.f;
#pragma unroll
        for (int j = 0; j < LL; j++) a = fmaf(sc[qi][j], vs[j * HD + d], a);
        out[base + (size_t)qi * HH + d] = a;
    }
}

// ---------------- LayerNorm + strip markers + scatter into processed ---------
__global__ __launch_bounds__(256)
void ln_scatter_kernel(const float* __restrict__ o, const float* __restrict__ gg,
                       const float* __restrict__ bb, float* __restrict__ proc) {
    const int row = blockIdx.x;
    const int l = row % LL;
    if (l == 0 || l == LL - 1) return;

    const float* x = o + (size_t)row * HH;
    const int t = threadIdx.x;
    float v0 = x[t], v1 = x[t + 256];
    float s = v0 + v1, ss = v0 * v0 + v1 * v1;
#pragma unroll
    for (int off = 16; off > 0; off >>= 1) {
        s  += __shfl_xor_sync(0xffffffffu, s,  off);
        ss += __shfl_xor_sync(0xffffffffu, ss, off);
    }
    __shared__ float sh_s[8], sh_ss[8];
    __shared__ float sh_mu, sh_inv;
    if ((t & 31) == 0) { sh_s[t >> 5] = s; sh_ss[t >> 5] = ss; }
    __syncthreads();
    if (t == 0) {
        float ts = 0.f, tss = 0.f;
#pragma unroll
        for (int w = 0; w < 8; w++) { ts += sh_s[w]; tss += sh_ss[w]; }
        float mu = ts / (float)HH;
        float var = tss / (float)HH - mu * mu;
        sh_mu = mu;
        sh_inv = rsqrtf(var + LN_EPS);
    }
    __syncthreads();
    float mu = sh_mu, inv = sh_inv;

    int n = row / LL;
    int b = n >> 8, seg = n & 255;
    size_t orow = (size_t)b * SS + (size_t)seg * SEG_LEN + (l - 1);
    float* dst = proc + orow * HH;
    dst[t]       = (v0 - mu) * inv * gg[t]       + bb[t];
    dst[t + 256] = (v1 - mu) * inv * gg[t + 256] + bb[t + 256];
}

// ---------------- copy last (reason tail) token rows -------------------------
__global__ void copy_last_kernel(const float* __restrict__ hid, float* __restrict__ proc) {
    size_t off = ((size_t)blockIdx.x * SS + (SS - 1)) * HH;
    for (int c = threadIdx.x; c < HH; c += blockDim.x) proc[off + c] = hid[off + c];
}

// ---------------- host launcher ----------------------------------------------
extern "C" void kernel_launch(void* const* d_in, const int* in_sizes, int n_in,
                              void* d_out, int out_size) {
    const float* hid  = (const float*)d_in[0];
    const float* st   = (const float*)d_in[3];
    const float* en   = (const float*)d_in[4];
    const float* Wq   = (const float*)d_in[5];
    const float* bq   = (const float*)d_in[6];
    const float* Wk   = (const float*)d_in[7];
    const float* bk   = (const float*)d_in[8];
    const float* Wv   = (const float*)d_in[9];
    const float* bv   = (const float*)d_in[10];
    const float* Wo   = (const float*)d_in[11];
    const float* bo   = (const float*)d_in[12];
    const float* lng  = (const float*)d_in[13];
    const float* lnb  = (const float*)d_in[14];
    const float* W1   = (const float*)d_in[15];
    const float* b1   = (const float*)d_in[16];
    const float* W2   = (const float*)d_in[17];
    const float* b2   = (const float*)d_in[18];
    float* out = (float*)d_out;

    float *segs, *q, *k, *v, *att, *o, *proc, *act;
    cudaGetSymbolAddress((void**)&segs, g_segs);
    cudaGetSymbolAddress((void**)&q,    g_q);
    cudaGetSymbolAddress((void**)&k,    g_k);
    cudaGetSymbolAddress((void**)&v,    g_v);
    cudaGetSymbolAddress((void**)&att,  g_att);
    cudaGetSymbolAddress((void**)&o,    g_o);
    cudaGetSymbolAddress((void**)&proc, g_proc);
    cudaGetSymbolAddress((void**)&act,  g_act);

    cudaFuncSetAttribute(tgemm_kernel<0>, cudaFuncAttributeMaxDynamicSharedMemorySize, GEMM_SMEM);
    cudaFuncSetAttribute(tgemm_kernel<1>, cudaFuncAttributeMaxDynamicSharedMemorySize, GEMM_SMEM);
    cudaFuncSetAttribute(tgemm_kernel<2>, cudaFuncAttributeMaxDynamicSharedMemorySize, GEMM_SMEM);

    // 1. gather segments + markers
    build_segs_kernel<<<(TOK * HH / 4) / 256, 256>>>(hid, st, en);

    // 2. fused QKV projection: one pass over A, 3 weight matrices
    {
        GemmMats m;
        m.W[0] = Wq; m.W[1] = Wk; m.W[2] = Wv;
        m.bias[0] = bq; m.bias[1] = bk; m.bias[2] = bv;
        m.C[0] = q; m.C[1] = k; m.C[2] = v;
        dim3 gqkv(3 * (HH / 256), TOK / 128);   // (6, 576)
        tgemm_kernel<0><<<gqkv, 256, GEMM_SMEM>>>(segs, m, HH / 256, nullptr, TOK, HH, HH);
    }

    // 3. per-(segment, head) attention
    attn_kernel<<<NSEG * NHH, 128>>>(q, k, v, att);

    // 4. output projection
    {
        GemmMats m;
        m.W[0] = Wo; m.bias[0] = bo; m.C[0] = o;
        m.W[1] = m.W[2] = nullptr; m.bias[1] = m.bias[2] = nullptr; m.C[1] = m.C[2] = nullptr;
        dim3 go(HH / 256, TOK / 128);
        tgemm_kernel<0><<<go, 256, GEMM_SMEM>>>(att, m, HH / 256, nullptr, TOK, HH, HH);
    }

    // 5. LayerNorm + scatter (strip markers), plus untouched final token rows
    ln_scatter_kernel<<<TOK, 256>>>(o, lng, lnb, proc);
    copy_last_kernel<<<BZ, 128>>>(hid, proc);

    // 6. FFN: gelu(proc @ W1 + b1) @ W2 + b2 + hidden
    {
        GemmMats m;
        m.W[0] = W1; m.bias[0] = b1; m.C[0] = act;
        m.W[1] = m.W[2] = nullptr; m.bias[1] = m.bias[2] = nullptr; m.C[1] = m.C[2] = nullptr;
        dim3 gf1(2 * HH / 256, (FTOK + 127) / 128);  // (4, 513)
        tgemm_kernel<1><<<gf1, 256, GEMM_SMEM>>>(proc, m, 2 * HH / 256, nullptr, FTOK, 2 * HH, HH);
    }
    {
        GemmMats m;
        m.W[0] = W2; m.bias[0] = b2; m.C[0] = out;
        m.W[1] = m.W[2] = nullptr; m.bias[1] = m.bias[2] = nullptr; m.C[1] = m.C[2] = nullptr;
        dim3 gf2(HH / 256, (FTOK + 127) / 128);      // (2, 513)
        tgemm_kernel<2><<<gf2, 256, GEMM_SMEM>>>(act, m, HH / 256, hid, FTOK, HH, 2 * HH);
    }
}

// round 9
// speedup vs baseline: 1.5508x; 1.5508x over previous
#include <cuda_runtime.h>
#include <cuda_fp16.h>
#include <math.h>
#include <stdint.h>

// Problem constants
#define BZ       16
#define SEG_LEN  16
#define NUM_SEGS 256
#define HH       512
#define NHH      8
#define HD       64
#define SS       4097                 // NUM_SEGS*SEG_LEN + 1
#define NSEG     (BZ * NUM_SEGS)     // 4096
#define LL       18                  // SEG_LEN + 2
#define TOK      (NSEG * LL)         // 73728
#define FTOK     (BZ * SS)           // 65552 (FFN tokens)
#define LN_EPS   1e-5f

// ---------------- scratch (__device__ globals) -------------------------------
__device__ __half g_segs[(size_t)TOK * HH];
__device__ __half g_q   [(size_t)TOK * HH];
__device__ __half g_k   [(size_t)TOK * HH];
__device__ __half g_v   [(size_t)TOK * HH];
__device__ __half g_att [(size_t)TOK * HH];
__device__ float  g_o   [(size_t)TOK * HH];
__device__ __half g_proc[(size_t)FTOK * HH];
__device__ __half g_act [(size_t)FTOK * 2 * HH];
// transposed fp16 weights [N][K] row-major
__device__ __half g_wqt[HH * HH];
__device__ __half g_wkt[HH * HH];
__device__ __half g_wvt[HH * HH];
__device__ __half g_wot[HH * HH];
__device__ __half g_w1t[2 * HH * HH];
__device__ __half g_w2t[2 * HH * HH];

// ---------------- build segs (fp32 -> fp16) ----------------------------------
__global__ void build_segs_kernel(const float* __restrict__ hid,
                                  const float* __restrict__ st,
                                  const float* __restrict__ en) {
    size_t i4 = (size_t)blockIdx.x * blockDim.x + threadIdx.x;
    int row = (int)(i4 / (HH / 4));
    int c4  = (int)(i4 % (HH / 4));
    int n = row / LL, l = row % LL;
    const float4* src;
    if (l == 0)            src = (const float4*)st;
    else if (l == LL - 1)  src = (const float4*)en;
    else {
        int b = n / NUM_SEGS, seg = n % NUM_SEGS;
        src = (const float4*)(hid + ((size_t)b * SS + (size_t)seg * SEG_LEN + (l - 1)) * HH);
    }
    float4 vv = src[c4];
    __half2* dst = (__half2*)g_segs + i4 * 2;
    dst[0] = __floats2half2_rn(vv.x, vv.y);
    dst[1] = __floats2half2_rn(vv.z, vv.w);
}

// ---------------- weight transpose+convert: src[K][N] f32 -> dst[N][K] f16 ---
__global__ __launch_bounds__(256)
void transpose_kernel(const float* __restrict__ src, __half* __restrict__ dst,
                      int K, int N) {
    __shared__ float t[32][33];
    int nb = blockIdx.x * 32, kb = blockIdx.y * 32;
    int tx = threadIdx.x & 31, ty = threadIdx.x >> 5;  // 32 x 8
#pragma unroll
    for (int i = 0; i < 32; i += 8)
        t[ty + i][tx] = src[(size_t)(kb + ty + i) * N + nb + tx];
    __syncthreads();
#pragma unroll
    for (int i = 0; i < 32; i += 8)
        dst[(size_t)(nb + ty + i) * K + kb + tx] = __float2half_rn(t[tx][ty + i]);
}

// ---------------- FP16 tensor-core GEMM (m16n8k16 + ldmatrix) ----------------
// C[M,N] = A[M,K] @ Wt[N,K]^T + bias (+epilogue)
// EPI: 0 = +bias ; 1 = gelu(x+bias) ; 2 = x+bias+res
__device__ __forceinline__ float gelu_exact(float x) {
    return 0.5f * x * (1.0f + erff(x * 0.70710678118654752f));
}
__device__ __forceinline__ uint32_t s2u(const void* p) {
    return (uint32_t)__cvta_generic_to_shared(p);
}
__device__ __forceinline__ void cpa16h(__half* smem_dst, const __half* gsrc) {
    uint32_t s = s2u(smem_dst);
    asm volatile("cp.async.cg.shared.global [%0], [%1], 16;\n" :: "r"(s), "l"(gsrc));
}

#define ASTRH   40                        // smem row stride in halves (80B: 5r mod 8 banks)
#define OP_STG  (128 * ASTRH)             // halves per operand per stage
#define HNSTG   4
#define GEMM_SMEM (2 * HNSTG * OP_STG * 2)   // 81,920 bytes

#define LDMX4(r0, r1, r2, r3, addr) \
    asm volatile("ldmatrix.sync.aligned.m8n8.x4.shared.b16 {%0,%1,%2,%3}, [%4];" \
                 : "=r"(r0), "=r"(r1), "=r"(r2), "=r"(r3) : "r"(addr))

template <int EPI, typename OutT>
__global__ __launch_bounds__(256, 2)
void hgemm_kernel(const __half* __restrict__ A, const __half* __restrict__ W,
                  const float* __restrict__ bias, const float* __restrict__ res,
                  OutT* __restrict__ C, int M, int N, int K) {
    extern __shared__ __half sh[];
    __half* As = sh;                     // [4][128][ASTRH]
    __half* Bs = sh + HNSTG * OP_STG;    // [4][128][ASTRH]

    const int tid  = threadIdx.x;
    const int warp = tid >> 5;
    const int lane = tid & 31;
    const int g    = lane >> 2;
    const int tig  = lane & 3;
    const int m0 = blockIdx.y * 128;
    const int n0 = blockIdx.x * 128;
    const int warp_m = (warp & 1) * 64;     // 2 warps in M
    const int warp_n = (warp >> 1) * 32;    // 4 warps in N

    // loaders: 2 threads per row, 16 halves (2 x 16B) each
    int arow = m0 + (tid >> 1); if (arow > M - 1) arow = M - 1;
    const __half* Ag = A + (size_t)arow * K + (tid & 1) * 16;
    const __half* Bg = W + (size_t)(n0 + (tid >> 1)) * K + (tid & 1) * 16;
    __half* Asd = As + (tid >> 1) * ASTRH + (tid & 1) * 16;
    __half* Bsd = Bs + (tid >> 1) * ASTRH + (tid & 1) * 16;

    const int nk = K >> 5;   // BK = 32 halves

    auto issue = [&](int kt) {
        int s = kt & 3;
        const __half* ga = Ag + kt * 32;
        __half* da = Asd + s * OP_STG;
        cpa16h(da, ga); cpa16h(da + 8, ga + 8);
        const __half* gb = Bg + kt * 32;
        __half* db = Bsd + s * OP_STG;
        cpa16h(db, gb); cpa16h(db + 8, gb + 8);
    };

    // ldmatrix per-lane offsets (in halves)
    const uint32_t a_off = ((lane & 7) + ((lane >> 3) & 1) * 8) * ASTRH + (lane >> 4) * 8;
    const uint32_t b_off = ((lane & 7) + ((lane >> 4) & 1) * 8) * ASTRH + ((lane >> 3) & 1) * 8;

    float acc[4][4][4];
#pragma unroll
    for (int i = 0; i < 4; i++)
#pragma unroll
        for (int j = 0; j < 4; j++)
#pragma unroll
            for (int c = 0; c < 4; c++) acc[i][j][c] = 0.f;

    // prologue: 3 stages in flight
#pragma unroll
    for (int p = 0; p < 3; p++) {
        issue(p);
        asm volatile("cp.async.commit_group;" ::: "memory");
    }

    for (int kt = 0; kt < nk; kt++) {
        asm volatile("cp.async.wait_group 2;" ::: "memory");
        __syncthreads();
        uint32_t asu = s2u(As + (kt & 3) * OP_STG);
        uint32_t bsu = s2u(Bs + (kt & 3) * OP_STG);
#pragma unroll
        for (int ks = 0; ks < 32; ks += 16) {
            uint32_t af[4][4], bf[4][2];
#pragma unroll
            for (int mt = 0; mt < 4; mt++) {
                uint32_t ad = asu + 2u * ((warp_m + mt * 16) * ASTRH + ks + a_off);
                LDMX4(af[mt][0], af[mt][1], af[mt][2], af[mt][3], ad);
            }
#pragma unroll
            for (int ntp = 0; ntp < 2; ntp++) {
                uint32_t bd = bsu + 2u * ((warp_n + ntp * 16) * ASTRH + ks + b_off);
                LDMX4(bf[ntp * 2][0], bf[ntp * 2][1],
                      bf[ntp * 2 + 1][0], bf[ntp * 2 + 1][1], bd);
            }
#pragma unroll
            for (int mt = 0; mt < 4; mt++)
#pragma unroll
                for (int nt = 0; nt < 4; nt++) {
                    asm volatile(
                        "mma.sync.aligned.m16n8k16.row.col.f32.f16.f16.f32 "
                        "{%0,%1,%2,%3}, {%4,%5,%6,%7}, {%8,%9}, {%0,%1,%2,%3};\n"
                        : "+f"(acc[mt][nt][0]), "+f"(acc[mt][nt][1]),
                          "+f"(acc[mt][nt][2]), "+f"(acc[mt][nt][3])
                        : "r"(af[mt][0]), "r"(af[mt][1]), "r"(af[mt][2]), "r"(af[mt][3]),
                          "r"(bf[nt][0]), "r"(bf[nt][1]));
                }
        }
        if (kt + 3 < nk) issue(kt + 3);
        asm volatile("cp.async.commit_group;" ::: "memory");   // may be empty (tail)
    }

    // epilogue
#pragma unroll
    for (int nt = 0; nt < 4; nt++) {
        int col = n0 + warp_n + nt * 8 + 2 * tig;
        float bx = bias[col], by = bias[col + 1];
#pragma unroll
        for (int mt = 0; mt < 4; mt++) {
            int r0 = m0 + warp_m + mt * 16 + g;
            int r1 = r0 + 8;
            float v0 = acc[mt][nt][0] + bx, v1 = acc[mt][nt][1] + by;
            float v2 = acc[mt][nt][2] + bx, v3 = acc[mt][nt][3] + by;
            if (EPI == 1) {
                v0 = gelu_exact(v0); v1 = gelu_exact(v1);
                v2 = gelu_exact(v2); v3 = gelu_exact(v3);
            }
            if (r0 < M) {
                if (EPI == 2) {
                    const float2 rr = *(const float2*)(res + (size_t)r0 * N + col);
                    v0 += rr.x; v1 += rr.y;
                }
                OutT* p = C + (size_t)r0 * N + col;
                if (sizeof(OutT) == 2) *(__half2*)p = __floats2half2_rn(v0, v1);
                else                   *(float2*)p  = make_float2(v0, v1);
            }
            if (r1 < M) {
                if (EPI == 2) {
                    const float2 rr = *(const float2*)(res + (size_t)r1 * N + col);
                    v2 += rr.x; v3 += rr.y;
                }
                OutT* p = C + (size_t)r1 * N + col;
                if (sizeof(OutT) == 2) *(__half2*)p = __floats2half2_rn(v2, v3);
                else                   *(float2*)p  = make_float2(v2, v3);
            }
        }
    }
}

// ---------------- attention per (segment, head), fp16 IO ---------------------
__global__ __launch_bounds__(128)
void attn_kernel(const __half* __restrict__ q, const __half* __restrict__ k,
                 const __half* __restrict__ v, __half* __restrict__ out) {
    const int n = blockIdx.x >> 3;
    const int h = blockIdx.x & 7;
    __shared__ float qs[LL * HD], ks[LL * HD], vs[LL * HD];
    __shared__ float sc[LL][LL];

    const size_t base = (size_t)n * LL * HH + (size_t)h * HD;
    for (int i = threadIdx.x; i < LL * HD; i += 128) {
        int r = i >> 6, c = i & 63;
        size_t idx = base + (size_t)r * HH + c;
        qs[i] = __half2float(q[idx]);
        ks[i] = __half2float(k[idx]);
        vs[i] = __half2float(v[idx]);
    }
    __syncthreads();

    for (int s = threadIdx.x; s < LL * LL; s += 128) {
        int qi = s / LL, kj = s % LL;
        float d = 0.f;
#pragma unroll
        for (int c = 0; c < HD; c++) d = fmaf(qs[qi * HD + c], ks[kj * HD + c], d);
        sc[qi][kj] = d * 0.125f;  // 1/sqrt(64)
    }
    __syncthreads();

    if (threadIdx.x < LL) {
        int r = threadIdx.x;
        float m = -1e30f;
#pragma unroll
        for (int j = 0; j < LL; j++) m = fmaxf(m, sc[r][j]);
        float sum = 0.f;
#pragma unroll
        for (int j = 0; j < LL; j++) { float e = __expf(sc[r][j] - m); sc[r][j] = e; sum += e; }
        float inv = 1.f / sum;
#pragma unroll
        for (int j = 0; j < LL; j++) sc[r][j] *= inv;
    }
    __syncthreads();

    for (int s = threadIdx.x; s < LL * HD; s += 128) {
        int qi = s >> 6, d = s & 63;
        float a = 0.f;
#pragma unroll
        for (int j = 0; j < LL; j++) a = fmaf(sc[qi][j], vs[j * HD + d], a);
        out[base + (size_t)qi * HH + d] = __float2half_rn(a);
    }
}

// ---------------- LayerNorm (fp32 in) + scatter to fp16 proc -----------------
__global__ __launch_bounds__(256)
void ln_scatter_kernel(const float* __restrict__ o, const float* __restrict__ gg,
                       const float* __restrict__ bb, __half* __restrict__ proc) {
    const int row = blockIdx.x;
    const int l = row % LL;
    if (l == 0 || l == LL - 1) return;

    const float* x = o + (size_t)row * HH;
    const int t = threadIdx.x;
    float v0 = x[t], v1 = x[t + 256];
    float s = v0 + v1, ss = v0 * v0 + v1 * v1;
#pragma unroll
    for (int off = 16; off > 0; off >>= 1) {
        s  += __shfl_xor_sync(0xffffffffu, s,  off);
        ss += __shfl_xor_sync(0xffffffffu, ss, off);
    }
    __shared__ float sh_s[8], sh_ss[8];
    __shared__ float sh_mu, sh_inv;
    if ((t & 31) == 0) { sh_s[t >> 5] = s; sh_ss[t >> 5] = ss; }
    __syncthreads();
    if (t == 0) {
        float ts = 0.f, tss = 0.f;
#pragma unroll
        for (int w = 0; w < 8; w++) { ts += sh_s[w]; tss += sh_ss[w]; }
        float mu = ts / (float)HH;
        float var = tss / (float)HH - mu * mu;
        sh_mu = mu;
        sh_inv = rsqrtf(var + LN_EPS);
    }
    __syncthreads();
    float mu = sh_mu, inv = sh_inv;

    int n = row / LL;
    int b = n >> 8, seg = n & 255;
    size_t orow = (size_t)b * SS + (size_t)seg * SEG_LEN + (l - 1);
    __half* dst = proc + orow * HH;
    dst[t]       = __float2half_rn((v0 - mu) * inv * gg[t]       + bb[t]);
    dst[t + 256] = __float2half_rn((v1 - mu) * inv * gg[t + 256] + bb[t + 256]);
}

// ---------------- copy last token rows (fp32 -> fp16) ------------------------
__global__ void copy_last_kernel(const float* __restrict__ hid, __half* __restrict__ proc) {
    size_t off = ((size_t)blockIdx.x * SS + (SS - 1)) * HH;
    for (int c = threadIdx.x; c < HH; c += blockDim.x)
        proc[off + c] = __float2half_rn(hid[off + c]);
}

// ---------------- host launcher ----------------------------------------------
extern "C" void kernel_launch(void* const* d_in, const int* in_sizes, int n_in,
                              void* d_out, int out_size) {
    const float* hid  = (const float*)d_in[0];
    const float* st   = (const float*)d_in[3];
    const float* en   = (const float*)d_in[4];
    const float* Wq   = (const float*)d_in[5];
    const float* bq   = (const float*)d_in[6];
    const float* Wk   = (const float*)d_in[7];
    const float* bk   = (const float*)d_in[8];
    const float* Wv   = (const float*)d_in[9];
    const float* bv   = (const float*)d_in[10];
    const float* Wo   = (const float*)d_in[11];
    const float* bo   = (const float*)d_in[12];
    const float* lng  = (const float*)d_in[13];
    const float* lnb  = (const float*)d_in[14];
    const float* W1   = (const float*)d_in[15];
    const float* b1   = (const float*)d_in[16];
    const float* W2   = (const float*)d_in[17];
    const float* b2   = (const float*)d_in[18];
    float* out = (float*)d_out;

    __half *segs, *q, *k, *v, *att, *proc, *act;
    __half *wqt, *wkt, *wvt, *wot, *w1t, *w2t;
    float  *o;
    cudaGetSymbolAddress((void**)&segs, g_segs);
    cudaGetSymbolAddress((void**)&q,    g_q);
    cudaGetSymbolAddress((void**)&k,    g_k);
    cudaGetSymbolAddress((void**)&v,    g_v);
    cudaGetSymbolAddress((void**)&att,  g_att);
    cudaGetSymbolAddress((void**)&o,    g_o);
    cudaGetSymbolAddress((void**)&proc, g_proc);
    cudaGetSymbolAddress((void**)&act,  g_act);
    cudaGetSymbolAddress((void**)&wqt,  g_wqt);
    cudaGetSymbolAddress((void**)&wkt,  g_wkt);
    cudaGetSymbolAddress((void**)&wvt,  g_wvt);
    cudaGetSymbolAddress((void**)&wot,  g_wot);
    cudaGetSymbolAddress((void**)&w1t,  g_w1t);
    cudaGetSymbolAddress((void**)&w2t,  g_w2t);

    cudaFuncSetAttribute((const void*)hgemm_kernel<0, __half>,
                         cudaFuncAttributeMaxDynamicSharedMemorySize, GEMM_SMEM);
    cudaFuncSetAttribute((const void*)hgemm_kernel<0, float>,
                         cudaFuncAttributeMaxDynamicSharedMemorySize, GEMM_SMEM);
    cudaFuncSetAttribute((const void*)hgemm_kernel<1, __half>,
                         cudaFuncAttributeMaxDynamicSharedMemorySize, GEMM_SMEM);
    cudaFuncSetAttribute((const void*)hgemm_kernel<2, float>,
                         cudaFuncAttributeMaxDynamicSharedMemorySize, GEMM_SMEM);

    // 0. transpose + fp16-convert weights -> [N][K]
    transpose_kernel<<<dim3(16, 16), 256>>>(Wq, wqt, HH, HH);
    transpose_kernel<<<dim3(16, 16), 256>>>(Wk, wkt, HH, HH);
    transpose_kernel<<<dim3(16, 16), 256>>>(Wv, wvt, HH, HH);
    transpose_kernel<<<dim3(16, 16), 256>>>(Wo, wot, HH, HH);
    transpose_kernel<<<dim3(32, 16), 256>>>(W1, w1t, HH, 2 * HH);
    transpose_kernel<<<dim3(16, 32), 256>>>(W2, w2t, 2 * HH, HH);

    // 1. gather segments + markers (fp16)
    build_segs_kernel<<<(TOK * HH / 4) / 256, 256>>>(hid, st, en);

    // 2. Q,K,V projections
    dim3 gproj(HH / 128, TOK / 128);   // (4, 576)
    hgemm_kernel<0, __half><<<gproj, 256, GEMM_SMEM>>>(segs, wqt, bq, nullptr, q, TOK, HH, HH);
    hgemm_kernel<0, __half><<<gproj, 256, GEMM_SMEM>>>(segs, wkt, bk, nullptr, k, TOK, HH, HH);
    hgemm_kernel<0, __half><<<gproj, 256, GEMM_SMEM>>>(segs, wvt, bv, nullptr, v, TOK, HH, HH);

    // 3. per-(segment, head) attention
    attn_kernel<<<NSEG * NHH, 128>>>(q, k, v, att);

    // 4. output projection (fp32 out for LN)
    hgemm_kernel<0, float><<<gproj, 256, GEMM_SMEM>>>(att, wot, bo, nullptr, o, TOK, HH, HH);

    // 5. LayerNorm + scatter, untouched tail token rows
    ln_scatter_kernel<<<TOK, 256>>>(o, lng, lnb, proc);
    copy_last_kernel<<<BZ, 128>>>(hid, proc);

    // 6. FFN
    dim3 gf1(2 * HH / 128, (FTOK + 127) / 128);  // (8, 513)
    hgemm_kernel<1, __half><<<gf1, 256, GEMM_SMEM>>>(proc, w1t, b1, nullptr, act, FTOK, 2 * HH, HH);
    dim3 gf2(HH / 128, (FTOK + 127) / 128);      // (4, 513)
    hgemm_kernel<2, float><<<gf2, 256, GEMM_SMEM>>>(act, w2t, b2, hid, out, FTOK, HH, 2 * HH);
}

// round 10
// speedup vs baseline: 2.0207x; 1.3030x over previous
#include <cuda_runtime.h>
#include <cuda_fp16.h>
#include <math.h>
#include <stdint.h>

// Problem constants
#define BZ       16
#define SEG_LEN  16
#define NUM_SEGS 256
#define HH       512
#define NHH      8
#define HD       64
#define SS       4097                 // NUM_SEGS*SEG_LEN + 1
#define NSEG     (BZ * NUM_SEGS)     // 4096
#define LL       18                  // SEG_LEN + 2
#define TOK      (NSEG * LL)         // 73728
#define FTOK     (BZ * SS)           // 65552 (FFN tokens)
#define QKVW     (3 * HH)            // 1536
#define LN_EPS   1e-5f

// ---------------- scratch (__device__ globals) -------------------------------
__device__ __half g_segs[(size_t)TOK * HH];
__device__ __half g_qkv [(size_t)TOK * QKVW];
__device__ __half g_att [(size_t)TOK * HH];
__device__ __half g_o   [(size_t)TOK * HH];
__device__ __half g_proc[(size_t)FTOK * HH];
__device__ __half g_act [(size_t)FTOK * 2 * HH];
// transposed fp16 weights [N][K] row-major
__device__ __half g_wqkvt[QKVW * HH];      // rows: 0-511 Wq^T, 512-1023 Wk^T, 1024-1535 Wv^T
__device__ __half g_wot[HH * HH];
__device__ __half g_w1t[2 * HH * HH];
__device__ __half g_w2t[2 * HH * HH];
__device__ float  g_bqkv[QKVW];

// ---------------- build segs (fp32 -> fp16) ----------------------------------
__global__ void build_segs_kernel(const float* __restrict__ hid,
                                  const float* __restrict__ st,
                                  const float* __restrict__ en) {
    size_t i4 = (size_t)blockIdx.x * blockDim.x + threadIdx.x;
    int row = (int)(i4 / (HH / 4));
    int c4  = (int)(i4 % (HH / 4));
    int n = row / LL, l = row % LL;
    const float4* src;
    if (l == 0)            src = (const float4*)st;
    else if (l == LL - 1)  src = (const float4*)en;
    else {
        int b = n / NUM_SEGS, seg = n % NUM_SEGS;
        src = (const float4*)(hid + ((size_t)b * SS + (size_t)seg * SEG_LEN + (l - 1)) * HH);
    }
    float4 vv = src[c4];
    __half2* dst = (__half2*)g_segs + i4 * 2;
    dst[0] = __floats2half2_rn(vv.x, vv.y);
    dst[1] = __floats2half2_rn(vv.z, vv.w);
}

// ---------------- weight transpose+convert: src[K][N] f32 -> dst[N][K] f16 ---
__global__ __launch_bounds__(256)
void transpose_kernel(const float* __restrict__ src, __half* __restrict__ dst,
                      int K, int N) {
    __shared__ float t[32][33];
    int nb = blockIdx.x * 32, kb = blockIdx.y * 32;
    int tx = threadIdx.x & 31, ty = threadIdx.x >> 5;  // 32 x 8
#pragma unroll
    for (int i = 0; i < 32; i += 8)
        t[ty + i][tx] = src[(size_t)(kb + ty + i) * N + nb + tx];
    __syncthreads();
#pragma unroll
    for (int i = 0; i < 32; i += 8)
        dst[(size_t)(nb + ty + i) * K + kb + tx] = __float2half_rn(t[tx][ty + i]);
}

// ---------------- FP16 tensor-core GEMM (m16n8k16 + ldmatrix) ----------------
// C[M,N] = A[M,K] @ Wt[N,K]^T + bias (+epilogue)
// EPI: 0 = +bias ; 1 = gelu(x+bias) ; 2 = x+bias+res
__device__ __forceinline__ float gelu_exact(float x) {
    return 0.5f * x * (1.0f + erff(x * 0.70710678118654752f));
}
__device__ __forceinline__ uint32_t s2u(const void* p) {
    return (uint32_t)__cvta_generic_to_shared(p);
}
__device__ __forceinline__ void cpa16h(__half* smem_dst, const __half* gsrc) {
    uint32_t s = s2u(smem_dst);
    asm volatile("cp.async.cg.shared.global [%0], [%1], 16;\n" :: "r"(s), "l"(gsrc));
}

#define ASTRH   40                        // smem row stride in halves (80B: 5r mod 8 banks)
#define OP_STG  (128 * ASTRH)             // halves per operand per stage
#define HNSTG   4
#define GEMM_SMEM (2 * HNSTG * OP_STG * 2)   // 81,920 bytes

#define LDMX4(r0, r1, r2, r3, addr) \
    asm volatile("ldmatrix.sync.aligned.m8n8.x4.shared.b16 {%0,%1,%2,%3}, [%4];" \
                 : "=r"(r0), "=r"(r1), "=r"(r2), "=r"(r3) : "r"(addr))

template <int EPI, typename OutT>
__global__ __launch_bounds__(256, 2)
void hgemm_kernel(const __half* __restrict__ A, const __half* __restrict__ W,
                  const float* __restrict__ bias, const float* __restrict__ res,
                  OutT* __restrict__ C, int M, int N, int K) {
    extern __shared__ __half sh[];
    __half* As = sh;                     // [4][128][ASTRH]
    __half* Bs = sh + HNSTG * OP_STG;    // [4][128][ASTRH]

    const int tid  = threadIdx.x;
    const int warp = tid >> 5;
    const int lane = tid & 31;
    const int g    = lane >> 2;
    const int tig  = lane & 3;
    const int m0 = blockIdx.y * 128;
    const int n0 = blockIdx.x * 128;
    const int warp_m = (warp & 1) * 64;     // 2 warps in M
    const int warp_n = (warp >> 1) * 32;    // 4 warps in N

    // loaders: 2 threads per row, 16 halves (2 x 16B) each
    int arow = m0 + (tid >> 1); if (arow > M - 1) arow = M - 1;
    const __half* Ag = A + (size_t)arow * K + (tid & 1) * 16;
    const __half* Bg = W + (size_t)(n0 + (tid >> 1)) * K + (tid & 1) * 16;
    __half* Asd = As + (tid >> 1) * ASTRH + (tid & 1) * 16;
    __half* Bsd = Bs + (tid >> 1) * ASTRH + (tid & 1) * 16;

    const int nk = K >> 5;   // BK = 32 halves

    auto issue = [&](int kt) {
        int s = kt & 3;
        const __half* ga = Ag + kt * 32;
        __half* da = Asd + s * OP_STG;
        cpa16h(da, ga); cpa16h(da + 8, ga + 8);
        const __half* gb = Bg + kt * 32;
        __half* db = Bsd + s * OP_STG;
        cpa16h(db, gb); cpa16h(db + 8, gb + 8);
    };

    // ldmatrix per-lane offsets (in halves)
    const uint32_t a_off = ((lane & 7) + ((lane >> 3) & 1) * 8) * ASTRH + (lane >> 4) * 8;
    const uint32_t b_off = ((lane & 7) + ((lane >> 4) & 1) * 8) * ASTRH + ((lane >> 3) & 1) * 8;

    float acc[4][4][4];
#pragma unroll
    for (int i = 0; i < 4; i++)
#pragma unroll
        for (int j = 0; j < 4; j++)
#pragma unroll
            for (int c = 0; c < 4; c++) acc[i][j][c] = 0.f;

    // prologue: 3 stages in flight
#pragma unroll
    for (int p = 0; p < 3; p++) {
        issue(p);
        asm volatile("cp.async.commit_group;" ::: "memory");
    }

    for (int kt = 0; kt < nk; kt++) {
        asm volatile("cp.async.wait_group 2;" ::: "memory");
        __syncthreads();
        uint32_t asu = s2u(As + (kt & 3) * OP_STG);
        uint32_t bsu = s2u(Bs + (kt & 3) * OP_STG);
#pragma unroll
        for (int ks = 0; ks < 32; ks += 16) {
            uint32_t af[4][4], bf[4][2];
#pragma unroll
            for (int mt = 0; mt < 4; mt++) {
                uint32_t ad = asu + 2u * ((warp_m + mt * 16) * ASTRH + ks + a_off);
                LDMX4(af[mt][0], af[mt][1], af[mt][2], af[mt][3], ad);
            }
#pragma unroll
            for (int ntp = 0; ntp < 2; ntp++) {
                uint32_t bd = bsu + 2u * ((warp_n + ntp * 16) * ASTRH + ks + b_off);
                LDMX4(bf[ntp * 2][0], bf[ntp * 2][1],
                      bf[ntp * 2 + 1][0], bf[ntp * 2 + 1][1], bd);
            }
#pragma unroll
            for (int mt = 0; mt < 4; mt++)
#pragma unroll
                for (int nt = 0; nt < 4; nt++) {
                    asm volatile(
                        "mma.sync.aligned.m16n8k16.row.col.f32.f16.f16.f32 "
                        "{%0,%1,%2,%3}, {%4,%5,%6,%7}, {%8,%9}, {%0,%1,%2,%3};\n"
                        : "+f"(acc[mt][nt][0]), "+f"(acc[mt][nt][1]),
                          "+f"(acc[mt][nt][2]), "+f"(acc[mt][nt][3])
                        : "r"(af[mt][0]), "r"(af[mt][1]), "r"(af[mt][2]), "r"(af[mt][3]),
                          "r"(bf[nt][0]), "r"(bf[nt][1]));
                }
        }
        if (kt + 3 < nk) issue(kt + 3);
        asm volatile("cp.async.commit_group;" ::: "memory");   // may be empty (tail)
    }

    // epilogue
#pragma unroll
    for (int nt = 0; nt < 4; nt++) {
        int col = n0 + warp_n + nt * 8 + 2 * tig;
        float bx = bias[col], by = bias[col + 1];
#pragma unroll
        for (int mt = 0; mt < 4; mt++) {
            int r0 = m0 + warp_m + mt * 16 + g;
            int r1 = r0 + 8;
            float v0 = acc[mt][nt][0] + bx, v1 = acc[mt][nt][1] + by;
            float v2 = acc[mt][nt][2] + bx, v3 = acc[mt][nt][3] + by;
            if (EPI == 1) {
                v0 = gelu_exact(v0); v1 = gelu_exact(v1);
                v2 = gelu_exact(v2); v3 = gelu_exact(v3);
            }
            if (r0 < M) {
                if (EPI == 2) {
                    const float2 rr = *(const float2*)(res + (size_t)r0 * N + col);
                    v0 += rr.x; v1 += rr.y;
                }
                OutT* p = C + (size_t)r0 * N + col;
                if (sizeof(OutT) == 2) *(__half2*)p = __floats2half2_rn(v0, v1);
                else                   *(float2*)p  = make_float2(v0, v1);
            }
            if (r1 < M) {
                if (EPI == 2) {
                    const float2 rr = *(const float2*)(res + (size_t)r1 * N + col);
                    v2 += rr.x; v3 += rr.y;
                }
                OutT* p = C + (size_t)r1 * N + col;
                if (sizeof(OutT) == 2) *(__half2*)p = __floats2half2_rn(v2, v3);
                else                   *(float2*)p  = make_float2(v2, v3);
            }
        }
    }
}

// ---------------- attention per (segment, head), packed qkv ------------------
#define PSTR 65   // padded smem row stride (floats) -> conflict-free dot products

__global__ __launch_bounds__(128)
void attn_kernel(const __half* __restrict__ qkv, __half* __restrict__ out) {
    const int n = blockIdx.x >> 3;
    const int h = blockIdx.x & 7;
    __shared__ float qs[LL * PSTR], ks[LL * PSTR], vs[LL * PSTR];
    __shared__ float sc[LL][LL];

    const size_t base = (size_t)n * LL * QKVW + (size_t)h * HD;
    // vectorized loads: 8 halves (16B) per thread-iteration, 8 iters/row
    for (int i = threadIdx.x; i < LL * 8; i += 128) {
        int r = i >> 3, c8 = i & 7;
        size_t gidx = base + (size_t)r * QKVW + c8 * 8;
        uint4 qv = *(const uint4*)(qkv + gidx);
        uint4 kv = *(const uint4*)(qkv + gidx + HH);
        uint4 vv = *(const uint4*)(qkv + gidx + 2 * HH);
        float* qd = &qs[r * PSTR + c8 * 8];
        float* kd = &ks[r * PSTR + c8 * 8];
        float* vd = &vs[r * PSTR + c8 * 8];
        const uint32_t* qw = (const uint32_t*)&qv;
        const uint32_t* kw = (const uint32_t*)&kv;
        const uint32_t* vw = (const uint32_t*)&vv;
#pragma unroll
        for (int j = 0; j < 4; j++) {
            float2 f;
            f = __half22float2(*(const __half2*)&qw[j]); qd[j*2] = f.x; qd[j*2+1] = f.y;
            f = __half22float2(*(const __half2*)&kw[j]); kd[j*2] = f.x; kd[j*2+1] = f.y;
            f = __half22float2(*(const __half2*)&vw[j]); vd[j*2] = f.x; vd[j*2+1] = f.y;
        }
    }
    __syncthreads();

    for (int s = threadIdx.x; s < LL * LL; s += 128) {
        int qi = s / LL, kj = s % LL;
        float d = 0.f;
#pragma unroll
        for (int c = 0; c < HD; c++) d = fmaf(qs[qi * PSTR + c], ks[kj * PSTR + c], d);
        sc[qi][kj] = d * 0.125f;  // 1/sqrt(64)
    }
    __syncthreads();

    if (threadIdx.x < LL) {
        int r = threadIdx.x;
        float m = -1e30f;
#pragma unroll
        for (int j = 0; j < LL; j++) m = fmaxf(m, sc[r][j]);
        float sum = 0.f;
#pragma unroll
        for (int j = 0; j < LL; j++) { float e = __expf(sc[r][j] - m); sc[r][j] = e; sum += e; }
        float inv = 1.f / sum;
#pragma unroll
        for (int j = 0; j < LL; j++) sc[r][j] *= inv;
    }
    __syncthreads();

    const size_t obase = (size_t)n * LL * HH + (size_t)h * HD;
    for (int s = threadIdx.x; s < LL * HD; s += 128) {
        int qi = s >> 6, d = s & 63;
        float a = 0.f;
#pragma unroll
        for (int j = 0; j < LL; j++) a = fmaf(sc[qi][j], vs[j * PSTR + d], a);
        out[obase + (size_t)qi * HH + d] = __float2half_rn(a);
    }
}

// ---------------- LayerNorm (fp16 in) + scatter to fp16 proc -----------------
__global__ __launch_bounds__(256)
void ln_scatter_kernel(const __half* __restrict__ o, const float* __restrict__ gg,
                       const float* __restrict__ bb, __half* __restrict__ proc) {
    const int row = blockIdx.x;
    const int l = row % LL;
    if (l == 0 || l == LL - 1) return;

    const __half* x = o + (size_t)row * HH;
    const int t = threadIdx.x;
    float v0 = __half2float(x[t]), v1 = __half2float(x[t + 256]);
    float s = v0 + v1, ss = v0 * v0 + v1 * v1;
#pragma unroll
    for (int off = 16; off > 0; off >>= 1) {
        s  += __shfl_xor_sync(0xffffffffu, s,  off);
        ss += __shfl_xor_sync(0xffffffffu, ss, off);
    }
    __shared__ float sh_s[8], sh_ss[8];
    __shared__ float sh_mu, sh_inv;
    if ((t & 31) == 0) { sh_s[t >> 5] = s; sh_ss[t >> 5] = ss; }
    __syncthreads();
    if (t == 0) {
        float ts = 0.f, tss = 0.f;
#pragma unroll
        for (int w = 0; w < 8; w++) { ts += sh_s[w]; tss += sh_ss[w]; }
        float mu = ts / (float)HH;
        float var = tss / (float)HH - mu * mu;
        sh_mu = mu;
        sh_inv = rsqrtf(var + LN_EPS);
    }
    __syncthreads();
    float mu = sh_mu, inv = sh_inv;

    int n = row / LL;
    int b = n >> 8, seg = n & 255;
    size_t orow = (size_t)b * SS + (size_t)seg * SEG_LEN + (l - 1);
    __half* dst = proc + orow * HH;
    dst[t]       = __float2half_rn((v0 - mu) * inv * gg[t]       + bb[t]);
    dst[t + 256] = __float2half_rn((v1 - mu) * inv * gg[t + 256] + bb[t + 256]);
}

// ---------------- copy last token rows (fp32 -> fp16) ------------------------
__global__ void copy_last_kernel(const float* __restrict__ hid, __half* __restrict__ proc) {
    size_t off = ((size_t)blockIdx.x * SS + (SS - 1)) * HH;
    for (int c = threadIdx.x; c < HH; c += blockDim.x)
        proc[off + c] = __float2half_rn(hid[off + c]);
}

// ---------------- host launcher ----------------------------------------------
extern "C" void kernel_launch(void* const* d_in, const int* in_sizes, int n_in,
                              void* d_out, int out_size) {
    const float* hid  = (const float*)d_in[0];
    const float* st   = (const float*)d_in[3];
    const float* en   = (const float*)d_in[4];
    const float* Wq   = (const float*)d_in[5];
    const float* bq   = (const float*)d_in[6];
    const float* Wk   = (const float*)d_in[7];
    const float* bk   = (const float*)d_in[8];
    const float* Wv   = (const float*)d_in[9];
    const float* bv   = (const float*)d_in[10];
    const float* Wo   = (const float*)d_in[11];
    const float* bo   = (const float*)d_in[12];
    const float* lng  = (const float*)d_in[13];
    const float* lnb  = (const float*)d_in[14];
    const float* W1   = (const float*)d_in[15];
    const float* b1   = (const float*)d_in[16];
    const float* W2   = (const float*)d_in[17];
    const float* b2   = (const float*)d_in[18];
    float* out = (float*)d_out;

    __half *segs, *qkv, *att, *o, *proc, *act;
    __half *wqkvt, *wot, *w1t, *w2t;
    float  *bqkv;
    cudaGetSymbolAddress((void**)&segs, g_segs);
    cudaGetSymbolAddress((void**)&qkv,  g_qkv);
    cudaGetSymbolAddress((void**)&att,  g_att);
    cudaGetSymbolAddress((void**)&o,    g_o);
    cudaGetSymbolAddress((void**)&proc, g_proc);
    cudaGetSymbolAddress((void**)&act,  g_act);
    cudaGetSymbolAddress((void**)&wqkvt, g_wqkvt);
    cudaGetSymbolAddress((void**)&wot,  g_wot);
    cudaGetSymbolAddress((void**)&w1t,  g_w1t);
    cudaGetSymbolAddress((void**)&w2t,  g_w2t);
    cudaGetSymbolAddress((void**)&bqkv, g_bqkv);

    cudaFuncSetAttribute((const void*)hgemm_kernel<0, __half>,
                         cudaFuncAttributeMaxDynamicSharedMemorySize, GEMM_SMEM);
    cudaFuncSetAttribute((const void*)hgemm_kernel<1, __half>,
                         cudaFuncAttributeMaxDynamicSharedMemorySize, GEMM_SMEM);
    cudaFuncSetAttribute((const void*)hgemm_kernel<2, float>,
                         cudaFuncAttributeMaxDynamicSharedMemorySize, GEMM_SMEM);

    // 0. transpose + fp16-convert weights; pack QKV weights & biases
    transpose_kernel<<<dim3(16, 16), 256>>>(Wq, wqkvt,                HH, HH);
    transpose_kernel<<<dim3(16, 16), 256>>>(Wk, wqkvt + HH * HH,      HH, HH);
    transpose_kernel<<<dim3(16, 16), 256>>>(Wv, wqkvt + 2 * HH * HH,  HH, HH);
    transpose_kernel<<<dim3(16, 16), 256>>>(Wo, wot, HH, HH);
    transpose_kernel<<<dim3(32, 16), 256>>>(W1, w1t, HH, 2 * HH);
    transpose_kernel<<<dim3(16, 32), 256>>>(W2, w2t, 2 * HH, HH);
    cudaMemcpyAsync(bqkv,          bq, HH * sizeof(float), cudaMemcpyDeviceToDevice);
    cudaMemcpyAsync(bqkv + HH,     bk, HH * sizeof(float), cudaMemcpyDeviceToDevice);
    cudaMemcpyAsync(bqkv + 2 * HH, bv, HH * sizeof(float), cudaMemcpyDeviceToDevice);

    // 1. gather segments + markers (fp16)
    build_segs_kernel<<<(TOK * HH / 4) / 256, 256>>>(hid, st, en);

    // 2. fused QKV projection: [TOK,512] @ [512,1536]
    dim3 gqkv(QKVW / 128, TOK / 128);   // (12, 576)
    hgemm_kernel<0, __half><<<gqkv, 256, GEMM_SMEM>>>(segs, wqkvt, bqkv, nullptr, qkv, TOK, QKVW, HH);

    // 3. per-(segment, head) attention (packed qkv input)
    attn_kernel<<<NSEG * NHH, 128>>>(qkv, att);

    // 4. output projection (fp16 out for LN)
    dim3 go(HH / 128, TOK / 128);
    hgemm_kernel<0, __half><<<go, 256, GEMM_SMEM>>>(att, wot, bo, nullptr, o, TOK, HH, HH);

    // 5. LayerNorm + scatter, untouched tail token rows
    ln_scatter_kernel<<<TOK, 256>>>(o, lng, lnb, proc);
    copy_last_kernel<<<BZ, 128>>>(hid, proc);

    // 6. FFN
    dim3 gf1(2 * HH / 128, (FTOK + 127) / 128);  // (8, 513)
    hgemm_kernel<1, __half><<<gf1, 256, GEMM_SMEM>>>(proc, w1t, b1, nullptr, act, FTOK, 2 * HH, HH);
    dim3 gf2(HH / 128, (FTOK + 127) / 128);      // (4, 513)
    hgemm_kernel<2, float><<<gf2, 256, GEMM_SMEM>>>(act, w2t, b2, hid, out, FTOK, HH, 2 * HH);
}